// round 9
// baseline (speedup 1.0000x reference)
#include <cuda_runtime.h>

#define WARPS_PER_BLOCK 8
#define ROWS_PER_WARP 16
#define ROWS_PER_BLOCK (WARPS_PER_BLOCK * ROWS_PER_WARP)   // 128

__device__ __forceinline__ float dot4(float4 a, float4 b) {
    return a.x*b.x + a.y*b.y + a.z*b.z + a.w*b.w;
}

// Packed reduction of 4 per-lane values across the warp. 9 SHFL total.
// PD valid on lane 0 only; PS/Q0/Q1 broadcast.
__device__ __forceinline__ void quad_reduce(float pd, float ps, float q0, float q1,
                                            int lane,
                                            float& PD, float& PS, float& Q0, float& Q1)
{
    const unsigned FULL = 0xFFFFFFFFu;
    const bool lo16 = (lane & 16) == 0;

    float a  = lo16 ? q0 : pd;
    float b  = lo16 ? q1 : ps;
    float ra = __shfl_xor_sync(FULL, a, 16);
    float rb = __shfl_xor_sync(FULL, b, 16);
    float u  = (lo16 ? pd : q0) + ra;
    float v  = (lo16 ? ps : q1) + rb;

    const bool lo8 = (lane & 8) == 0;
    float c  = lo8 ? v : u;
    float rc = __shfl_xor_sync(FULL, c, 8);
    float s  = (lo8 ? u : v) + rc;

    s += __shfl_xor_sync(FULL, s, 4);
    s += __shfl_xor_sync(FULL, s, 2);
    s += __shfl_xor_sync(FULL, s, 1);

    PD = s;                           // valid on lane 0
    PS = __shfl_sync(FULL, s, 8);
    Q0 = __shfl_sync(FULL, s, 16);
    Q1 = __shfl_sync(FULL, s, 24);
}

template <bool WRAP>
__device__ __forceinline__ void warp_body(
    const float4* __restrict__ X4, const float4* __restrict__ T4,
    const float* __restrict__ f_bias,
    const float4* __restrict__ xis,     // smem: xi row0 [0..32), row1 [32..64)
    float gb0, float gb1,
    int base, int lane, int N,
    float2* __restrict__ vfirst_slot, float2* __restrict__ obuf_w,
    float& wd_p, float& ws_p, float& v0_p, float& v1_p)
{
    auto gidx = [&](int r) -> int {
        int g = base + r;
        if (WRAP && g >= N) g -= N;
        return g;
    };

    float4 x_cur = __ldcs(X4 + (size_t)gidx(0) * 32 + lane);
    float4 t_cur = __ldcs(T4 + (size_t)gidx(0) * 32 + lane);
    float4 t_nxt = __ldcs(T4 + (size_t)gidx(1) * 32 + lane);
    float  fb_cur = __ldg(f_bias + gidx(0));

    wd_p = 0.0f; ws_p = 0.0f; v0_p = 0.0f; v1_p = 0.0f;

    #pragma unroll
    for (int r = 0; r < ROWS_PER_WARP; r++) {
        // Prefetch next iteration (distance 1); fast path = base+immediate.
        float4 x_nx, t_nx2;
        if (r < ROWS_PER_WARP - 1) {
            x_nx  = __ldcs(X4 + (size_t)gidx(r + 1) * 32 + lane);
            t_nx2 = __ldcs(T4 + (size_t)gidx(r + 2) * 32 + lane);
        }
        const float fb_nxt = __ldg(f_bias + gidx(r + 1));

        const float4 w0 = xis[lane];        // LDS.128 broadcast-free
        const float4 w1 = xis[32 + lane];

        float pd = dot4(x_cur, t_cur);
        float ps = dot4(x_cur, t_nxt);
        float q0 = dot4(x_cur, w0);
        float q1 = dot4(x_cur, w1);

        float PD, PS, Q0, Q1;
        quad_reduce(pd, ps, q0, q1, lane, PD, PS, Q0, Q1);

        const float wd = fmaxf(PD + fb_cur, 0.0f);   // lane 0 valid
        const float ws = fmaxf(PS + fb_nxt, 0.0f);
        const float v0 = fmaxf(Q0 + gb0, 0.0f);
        const float v1 = fmaxf(Q1 + gb1, 0.0f);

        if (r == 0) {
            if (lane == 0)
                *vfirst_slot = make_float2(v0, v1);
        } else if (lane == 0) {
            obuf_w[r - 1] = make_float2(wd_p * v0_p + ws_p * v0,
                                        wd_p * v1_p + ws_p * v1);
        }

        wd_p = wd; ws_p = ws; v0_p = v0; v1_p = v1;
        fb_cur = fb_nxt;
        if (r < ROWS_PER_WARP - 1) {
            x_cur = x_nx;
            t_cur = t_nxt;
            t_nxt = t_nx2;
        }
    }
}

__global__ __launch_bounds__(WARPS_PER_BLOCK * 32, 6)
void smf_kernel(const float* __restrict__ X,
                const float* __restrict__ theta,
                const float* __restrict__ f_bias,
                const float* __restrict__ xi,
                const float* __restrict__ g_bias,
                float* __restrict__ out,
                int N)
{
    __shared__ float4 xis[64];                          // xi: 2 x 128 floats
    __shared__ float2 Vfirst[WARPS_PER_BLOCK];
    __shared__ float2 obuf[WARPS_PER_BLOCK][ROWS_PER_WARP];

    const int warp = threadIdx.x >> 5;
    const int lane = threadIdx.x & 31;
    const int base = (blockIdx.x * WARPS_PER_BLOCK + warp) * ROWS_PER_WARP;

    const float4* __restrict__ X4  = reinterpret_cast<const float4*>(X);
    const float4* __restrict__ T4  = reinterpret_cast<const float4*>(theta);
    const float4* __restrict__ XI4 = reinterpret_cast<const float4*>(xi);

    if (threadIdx.x < 64)
        xis[threadIdx.x] = XI4[threadIdx.x];

    const float gb0 = g_bias[0];
    const float gb1 = g_bias[1];

    __syncthreads();   // xis visible

    float wd_p, ws_p, v0_p, v1_p;
    if (base + ROWS_PER_WARP < N) {
        warp_body<false>(X4, T4, f_bias, xis, gb0, gb1, base, lane, N,
                         &Vfirst[warp], obuf[warp], wd_p, ws_p, v0_p, v1_p);
    } else {
        warp_body<true>(X4, T4, f_bias, xis, gb0, gb1, base, lane, N,
                        &Vfirst[warp], obuf[warp], wd_p, ws_p, v0_p, v1_p);
    }

    // Final row of this warp needs V[base + ROWS_PER_WARP]
    float2 vnext = make_float2(0.0f, 0.0f);
    if (warp == WARPS_PER_BLOCK - 1) {
        int h = base + ROWS_PER_WARP;
        if (h >= N) h -= N;
        const float4 xh = __ldcs(X4 + (size_t)h * 32 + lane);
        const float4 w0 = xis[lane];
        const float4 w1 = xis[32 + lane];
        float h0 = dot4(xh, w0);
        float h1 = dot4(xh, w1);
        float H0, H1, D0, D1;
        quad_reduce(h0, h1, 0.0f, 0.0f, lane, H0, H1, D0, D1);
        if (lane == 0)
            vnext = make_float2(fmaxf(H0 + gb0, 0.0f), fmaxf(H1 + gb1, 0.0f));
    }
    __syncthreads();

    if (lane == 0) {
        if (warp < WARPS_PER_BLOCK - 1)
            vnext = Vfirst[warp + 1];
        obuf[warp][ROWS_PER_WARP - 1] = make_float2(wd_p * v0_p + ws_p * vnext.x,
                                                    wd_p * v1_p + ws_p * vnext.y);
    }
    __syncwarp();

    // Coalesced store: 16 lanes write the warp's 16 float2 results (128B)
    if (lane < ROWS_PER_WARP)
        reinterpret_cast<float2*>(out)[base + lane] = obuf[warp][lane];
}

extern "C" void kernel_launch(void* const* d_in, const int* in_sizes, int n_in,
                              void* d_out, int out_size)
{
    const float* X      = (const float*)d_in[0];
    const float* theta  = (const float*)d_in[1];
    const float* f_bias = (const float*)d_in[2];
    const float* xi     = (const float*)d_in[3];
    const float* g_bias = (const float*)d_in[4];
    float* out = (float*)d_out;

    const int N = in_sizes[2];                   // f_bias has N elements
    const int blocks = N / ROWS_PER_BLOCK;       // 524288 / 128 = 4096

    smf_kernel<<<blocks, WARPS_PER_BLOCK * 32>>>(X, theta, f_bias, xi, g_bias, out, N);
}

// round 10
// speedup vs baseline: 1.0323x; 1.0323x over previous
#include <cuda_runtime.h>
#include <cstdint>

#define WARPS_PER_BLOCK 8
#define ROWS_PER_WARP 16
#define ROWS_PER_BLOCK (WARPS_PER_BLOCK * ROWS_PER_WARP)   // 128

__device__ __forceinline__ float dot4(float4 a, float4 b) {
    return a.x*b.x + a.y*b.y + a.z*b.z + a.w*b.w;
}

// Packed reduction of 4 per-lane values across the warp. 9 SHFL total.
// PD returned valid on lane 0 only; PS/Q0/Q1 broadcast to all lanes.
__device__ __forceinline__ void quad_reduce(float pd, float ps, float q0, float q1,
                                            int lane,
                                            float& PD, float& PS, float& Q0, float& Q1)
{
    const unsigned FULL = 0xFFFFFFFFu;
    const bool lo16 = (lane & 16) == 0;

    float a  = lo16 ? q0 : pd;
    float b  = lo16 ? q1 : ps;
    float ra = __shfl_xor_sync(FULL, a, 16);
    float rb = __shfl_xor_sync(FULL, b, 16);
    float u  = (lo16 ? pd : q0) + ra;
    float v  = (lo16 ? ps : q1) + rb;

    const bool lo8 = (lane & 8) == 0;
    float c  = lo8 ? v : u;
    float rc = __shfl_xor_sync(FULL, c, 8);
    float s  = (lo8 ? u : v) + rc;

    s += __shfl_xor_sync(FULL, s, 4);
    s += __shfl_xor_sync(FULL, s, 2);
    s += __shfl_xor_sync(FULL, s, 1);

    PD = s;                           // valid on lane 0
    PS = __shfl_sync(FULL, s, 8);
    Q0 = __shfl_sync(FULL, s, 16);
    Q1 = __shfl_sync(FULL, s, 24);
}

__global__ __launch_bounds__(WARPS_PER_BLOCK * 32, 6)
void smf_kernel(const float* __restrict__ X,
                const float* __restrict__ theta,
                const float* __restrict__ f_bias,
                const float* __restrict__ xi,
                const float* __restrict__ g_bias,
                float* __restrict__ out,
                unsigned mask)          // N-1 ; N is a power of two (524288)
{
    __shared__ float4 xis[64];                          // xi: 2 x 128 floats
    __shared__ float2 Vfirst[WARPS_PER_BLOCK];          // V of each warp's first row
    __shared__ float2 obuf[WARPS_PER_BLOCK][ROWS_PER_WARP];

    const int warp = threadIdx.x >> 5;
    const int lane = threadIdx.x & 31;
    const int base = (blockIdx.x * WARPS_PER_BLOCK + warp) * ROWS_PER_WARP;

    const float4* __restrict__ X4  = reinterpret_cast<const float4*>(X);
    const float4* __restrict__ T4  = reinterpret_cast<const float4*>(theta);
    const float4* __restrict__ XI4 = reinterpret_cast<const float4*>(xi);

    if (threadIdx.x < 64)
        xis[threadIdx.x] = XI4[threadIdx.x];

    const float gb0 = g_bias[0];
    const float gb1 = g_bias[1];

    // Pipeline state (depth 1): current X row, diag theta, sup theta
    float4 x_cur = __ldcs(X4 + (size_t)base * 32 + lane);
    float4 t_cur = __ldcs(T4 + (size_t)base * 32 + lane);
    float4 t_nxt = __ldcs(T4 + (size_t)((unsigned)(base + 1) & mask) * 32 + lane);
    float  fb_cur = __ldg(f_bias + base);

    __syncthreads();   // xis visible

    float wd_p = 0.0f, ws_p = 0.0f, v0_p = 0.0f, v1_p = 0.0f;

    #pragma unroll
    for (int r = 0; r < ROWS_PER_WARP; r++) {
        const int row = base + r;
        const unsigned rn = (unsigned)(row + 1) & mask;

        // Prefetch next iteration (distance 1)
        float4 x_nx, t_nx2;
        if (r < ROWS_PER_WARP - 1) {
            x_nx = __ldcs(X4 + (size_t)(row + 1) * 32 + lane);
            const unsigned i2 = (unsigned)(row + 2) & mask;
            t_nx2 = __ldcs(T4 + (size_t)i2 * 32 + lane);
        }
        const float fb_nxt = __ldg(f_bias + rn);

        const float4 w0 = xis[lane];
        const float4 w1 = xis[32 + lane];

        float pd = dot4(x_cur, t_cur);
        float ps = dot4(x_cur, t_nxt);
        float q0 = dot4(x_cur, w0);
        float q1 = dot4(x_cur, w1);

        float PD, PS, Q0, Q1;
        quad_reduce(pd, ps, q0, q1, lane, PD, PS, Q0, Q1);

        const float wd = fmaxf(PD + fb_cur, 0.0f);   // lane 0 valid
        const float ws = fmaxf(PS + fb_nxt, 0.0f);
        const float v0 = fmaxf(Q0 + gb0, 0.0f);
        const float v1 = fmaxf(Q1 + gb1, 0.0f);

        if (r == 0) {
            if (lane == 0)
                Vfirst[warp] = make_float2(v0, v1);
        } else if (lane == 0) {
            obuf[warp][r - 1] = make_float2(wd_p * v0_p + ws_p * v0,
                                            wd_p * v1_p + ws_p * v1);
        }

        wd_p = wd; ws_p = ws; v0_p = v0; v1_p = v1;
        fb_cur = fb_nxt;
        if (r < ROWS_PER_WARP - 1) {
            x_cur = x_nx;
            t_cur = t_nxt;
            t_nxt = t_nx2;
        }
    }

    // Final row of this warp needs V[base + ROWS_PER_WARP]
    float2 vnext = make_float2(0.0f, 0.0f);
    if (warp == WARPS_PER_BLOCK - 1) {
        const unsigned h = (unsigned)(base + ROWS_PER_WARP) & mask;
        const float4 xh = __ldcs(X4 + (size_t)h * 32 + lane);
        const float4 w0 = xis[lane];
        const float4 w1 = xis[32 + lane];
        float h0 = dot4(xh, w0);
        float h1 = dot4(xh, w1);
        float H0, H1, D0, D1;
        quad_reduce(h0, h1, 0.0f, 0.0f, lane, H0, H1, D0, D1);
        if (lane == 0)
            vnext = make_float2(fmaxf(H0 + gb0, 0.0f), fmaxf(H1 + gb1, 0.0f));
    }
    __syncthreads();

    if (lane == 0) {
        if (warp < WARPS_PER_BLOCK - 1)
            vnext = Vfirst[warp + 1];
        obuf[warp][ROWS_PER_WARP - 1] = make_float2(wd_p * v0_p + ws_p * vnext.x,
                                                    wd_p * v1_p + ws_p * vnext.y);
    }
    __syncwarp();

    // Coalesced store: 16 lanes write the warp's 16 float2 results (128B)
    if (lane < ROWS_PER_WARP)
        reinterpret_cast<float2*>(out)[base + lane] = obuf[warp][lane];
}

// ---- Fallback for non-power-of-two N (identical to the R7 baseline) ----
__global__ __launch_bounds__(WARPS_PER_BLOCK * 32, 6)
void smf_kernel_gen(const float* __restrict__ X,
                    const float* __restrict__ theta,
                    const float* __restrict__ f_bias,
                    const float* __restrict__ xi,
                    const float* __restrict__ g_bias,
                    float* __restrict__ out,
                    int N)
{
    __shared__ float4 xis[64];
    __shared__ float2 Vfirst[WARPS_PER_BLOCK];
    __shared__ float2 obuf[WARPS_PER_BLOCK][ROWS_PER_WARP];

    const int warp = threadIdx.x >> 5;
    const int lane = threadIdx.x & 31;
    const int base = (blockIdx.x * WARPS_PER_BLOCK + warp) * ROWS_PER_WARP;

    const float4* __restrict__ X4  = reinterpret_cast<const float4*>(X);
    const float4* __restrict__ T4  = reinterpret_cast<const float4*>(theta);
    const float4* __restrict__ XI4 = reinterpret_cast<const float4*>(xi);

    if (threadIdx.x < 64)
        xis[threadIdx.x] = XI4[threadIdx.x];

    const float gb0 = g_bias[0];
    const float gb1 = g_bias[1];

    float4 x_cur = __ldcs(X4 + (size_t)base * 32 + lane);
    float4 t_cur = __ldcs(T4 + (size_t)base * 32 + lane);
    float4 t_nxt = __ldcs(T4 + (size_t)(base + 1) * 32 + lane);
    float  fb_cur = __ldg(f_bias + base);

    __syncthreads();

    float wd_p = 0.0f, ws_p = 0.0f, v0_p = 0.0f, v1_p = 0.0f;

    #pragma unroll
    for (int r = 0; r < ROWS_PER_WARP; r++) {
        const int row = base + r;
        int rn = row + 1;
        if (rn >= N) rn -= N;

        float4 x_nx, t_nx2;
        if (r < ROWS_PER_WARP - 1) {
            x_nx = __ldcs(X4 + (size_t)(row + 1) * 32 + lane);
            int i2 = row + 2;
            if (i2 >= N) i2 -= N;
            t_nx2 = __ldcs(T4 + (size_t)i2 * 32 + lane);
        }
        const float fb_nxt = __ldg(f_bias + rn);

        const float4 w0 = xis[lane];
        const float4 w1 = xis[32 + lane];

        float pd = dot4(x_cur, t_cur);
        float ps = dot4(x_cur, t_nxt);
        float q0 = dot4(x_cur, w0);
        float q1 = dot4(x_cur, w1);

        float PD, PS, Q0, Q1;
        quad_reduce(pd, ps, q0, q1, lane, PD, PS, Q0, Q1);

        const float wd = fmaxf(PD + fb_cur, 0.0f);
        const float ws = fmaxf(PS + fb_nxt, 0.0f);
        const float v0 = fmaxf(Q0 + gb0, 0.0f);
        const float v1 = fmaxf(Q1 + gb1, 0.0f);

        if (r == 0) {
            if (lane == 0)
                Vfirst[warp] = make_float2(v0, v1);
        } else if (lane == 0) {
            obuf[warp][r - 1] = make_float2(wd_p * v0_p + ws_p * v0,
                                            wd_p * v1_p + ws_p * v1);
        }

        wd_p = wd; ws_p = ws; v0_p = v0; v1_p = v1;
        fb_cur = fb_nxt;
        if (r < ROWS_PER_WARP - 1) {
            x_cur = x_nx;
            t_cur = t_nxt;
            t_nxt = t_nx2;
        }
    }

    float2 vnext = make_float2(0.0f, 0.0f);
    if (warp == WARPS_PER_BLOCK - 1) {
        int h = base + ROWS_PER_WARP;
        if (h >= N) h -= N;
        const float4 xh = __ldcs(X4 + (size_t)h * 32 + lane);
        const float4 w0 = xis[lane];
        const float4 w1 = xis[32 + lane];
        float h0 = dot4(xh, w0);
        float h1 = dot4(xh, w1);
        float H0, H1, D0, D1;
        quad_reduce(h0, h1, 0.0f, 0.0f, lane, H0, H1, D0, D1);
        if (lane == 0)
            vnext = make_float2(fmaxf(H0 + gb0, 0.0f), fmaxf(H1 + gb1, 0.0f));
    }
    __syncthreads();

    if (lane == 0) {
        if (warp < WARPS_PER_BLOCK - 1)
            vnext = Vfirst[warp + 1];
        obuf[warp][ROWS_PER_WARP - 1] = make_float2(wd_p * v0_p + ws_p * vnext.x,
                                                    wd_p * v1_p + ws_p * vnext.y);
    }
    __syncwarp();

    if (lane < ROWS_PER_WARP)
        reinterpret_cast<float2*>(out)[base + lane] = obuf[warp][lane];
}

extern "C" void kernel_launch(void* const* d_in, const int* in_sizes, int n_in,
                              void* d_out, int out_size)
{
    const float* X      = (const float*)d_in[0];
    const float* theta  = (const float*)d_in[1];
    const float* f_bias = (const float*)d_in[2];
    const float* xi     = (const float*)d_in[3];
    const float* g_bias = (const float*)d_in[4];
    float* out = (float*)d_out;

    const int N = in_sizes[2];                   // f_bias has N elements
    const int blocks = N / ROWS_PER_BLOCK;       // 524288 / 128 = 4096

    if ((N & (N - 1)) == 0) {
        smf_kernel<<<blocks, WARPS_PER_BLOCK * 32>>>(X, theta, f_bias, xi, g_bias,
                                                     out, (unsigned)(N - 1));
    } else {
        smf_kernel_gen<<<blocks, WARPS_PER_BLOCK * 32>>>(X, theta, f_bias, xi, g_bias,
                                                         out, N);
    }
}

// round 11
// speedup vs baseline: 1.1045x; 1.0699x over previous
#include <cuda_runtime.h>

#define WARPS_PER_BLOCK 8
#define PAIRS 8
#define ROWS_PER_WARP (2 * PAIRS)                           // 16
#define ROWS_PER_BLOCK (WARPS_PER_BLOCK * ROWS_PER_WARP)    // 128

__device__ __forceinline__ float dot4(float4 a, float4 b) {
    return a.x*b.x + a.y*b.y + a.z*b.z + a.w*b.w;
}

// 8-value packed warp reduction, 9 SHFL. After return, every lane in 4-lane
// group g (= lane>>2) holds the warp-total of slot g.
__device__ __forceinline__ float oct_reduce(const float v[8], int lane)
{
    const unsigned F = 0xFFFFFFFFu;
    const bool lo16 = (lane & 16) == 0;
    float s0, s1, s2, s3;
    {
        float e0 = lo16 ? v[4] : v[0];
        float e1 = lo16 ? v[5] : v[1];
        float e2 = lo16 ? v[6] : v[2];
        float e3 = lo16 ? v[7] : v[3];
        float r0 = __shfl_xor_sync(F, e0, 16);
        float r1 = __shfl_xor_sync(F, e1, 16);
        float r2 = __shfl_xor_sync(F, e2, 16);
        float r3 = __shfl_xor_sync(F, e3, 16);
        s0 = (lo16 ? v[0] : v[4]) + r0;
        s1 = (lo16 ? v[1] : v[5]) + r1;
        s2 = (lo16 ? v[2] : v[6]) + r2;
        s3 = (lo16 ? v[3] : v[7]) + r3;
    }
    const bool lo8 = (lane & 8) == 0;
    float u0, u1;
    {
        float e0 = lo8 ? s2 : s0;
        float e1 = lo8 ? s3 : s1;
        float r0 = __shfl_xor_sync(F, e0, 8);
        float r1 = __shfl_xor_sync(F, e1, 8);
        u0 = (lo8 ? s0 : s2) + r0;
        u1 = (lo8 ? s1 : s3) + r1;
    }
    const bool lo4 = (lane & 4) == 0;
    float t;
    {
        float e = lo4 ? u1 : u0;
        float r = __shfl_xor_sync(F, e, 4);
        t = (lo4 ? u0 : u1) + r;
    }
    t += __shfl_xor_sync(F, t, 2);
    t += __shfl_xor_sync(F, t, 1);
    return t;
}

// 4-value reduction (halo only). PD valid on lane 0; PS broadcast.
__device__ __forceinline__ void quad_reduce(float pd, float ps, float q0, float q1,
                                            int lane, float& PD, float& PS)
{
    const unsigned F = 0xFFFFFFFFu;
    const bool lo16 = (lane & 16) == 0;
    float a  = lo16 ? q0 : pd;
    float b  = lo16 ? q1 : ps;
    float ra = __shfl_xor_sync(F, a, 16);
    float rb = __shfl_xor_sync(F, b, 16);
    float u  = (lo16 ? pd : q0) + ra;
    float v  = (lo16 ? ps : q1) + rb;
    const bool lo8 = (lane & 8) == 0;
    float c  = lo8 ? v : u;
    float rc = __shfl_xor_sync(F, c, 8);
    float s  = (lo8 ? u : v) + rc;
    s += __shfl_xor_sync(F, s, 4);
    s += __shfl_xor_sync(F, s, 2);
    s += __shfl_xor_sync(F, s, 1);
    PD = s;                          // lane 0
    PS = __shfl_sync(F, s, 8);
}

__global__ __launch_bounds__(WARPS_PER_BLOCK * 32)
void smf_kernel(const float* __restrict__ X,
                const float* __restrict__ theta,
                const float* __restrict__ f_bias,
                const float* __restrict__ xi,
                const float* __restrict__ g_bias,
                float* __restrict__ out,
                int N)
{
    __shared__ float4 xis[64];                      // xi: 2 x 128 floats
    __shared__ float2 Vnext[WARPS_PER_BLOCK + 1];   // [w]=warp w first-row V, [8]=halo
    __shared__ float2 obuf[WARPS_PER_BLOCK][ROWS_PER_WARP];

    const unsigned F = 0xFFFFFFFFu;
    const int warp = threadIdx.x >> 5;
    const int lane = threadIdx.x & 31;
    const int base = (blockIdx.x * WARPS_PER_BLOCK + warp) * ROWS_PER_WARP;

    const float4* __restrict__ X4  = reinterpret_cast<const float4*>(X);
    const float4* __restrict__ T4  = reinterpret_cast<const float4*>(theta);
    const float4* __restrict__ XI4 = reinterpret_cast<const float4*>(xi);

    if (threadIdx.x < 64)
        xis[threadIdx.x] = XI4[threadIdx.x];

    const float gb0 = g_bias[0];
    const float gb1 = g_bias[1];

    // Steady state: rows 2p, 2p+1 of this warp.
    float4 x_a = __ldcs(X4 + (size_t)base * 32 + lane);
    float4 x_b = __ldcs(X4 + (size_t)(base + 1) * 32 + lane);
    float4 t0  = __ldcs(T4 + (size_t)base * 32 + lane);
    float4 t1  = __ldcs(T4 + (size_t)(base + 1) * 32 + lane);
    float4 t2  = __ldcs(T4 + (size_t)(base + 2) * 32 + lane);
    float fb_a = __ldg(f_bias + base);
    float fb_b = __ldg(f_bias + base + 1);

    __syncthreads();   // xis visible

    const int g  = lane >> 2;
    const int hi = lane & 16;

    float wdb = 0.0f, wsb = 0.0f, v0b = 0.0f, v1b = 0.0f;   // carry (lane 16)

    #pragma unroll
    for (int p = 0; p < PAIRS; p++) {
        const int ra = base + 2 * p;

        int ic = ra + 2;
        if (ic >= N) ic -= N;                    // only last warp, p==7
        const float fb_c = __ldg(f_bias + ic);

        // Prefetch next pair's state (distance 1 pair)
        float4 x_na, x_nb, t_n3, t_n4;
        float fb_n;
        if (p < PAIRS - 1) {
            x_na = __ldcs(X4 + (size_t)(ra + 2) * 32 + lane);
            x_nb = __ldcs(X4 + (size_t)(ra + 3) * 32 + lane);
            t_n3 = __ldcs(T4 + (size_t)(ra + 3) * 32 + lane);
            int i4 = ra + 4;
            if (i4 >= N) i4 -= N;
            t_n4 = __ldcs(T4 + (size_t)i4 * 32 + lane);
            fb_n = __ldg(f_bias + (ra + 3));
        }

        const float4 w0 = xis[lane];
        const float4 w1 = xis[32 + lane];

        float v[8];
        v[0] = dot4(x_a, t0);    // pd_a
        v[1] = dot4(x_a, t1);    // ps_a
        v[2] = dot4(x_a, w0);    // q0_a
        v[3] = dot4(x_a, w1);    // q1_a
        v[4] = dot4(x_b, t1);    // pd_b
        v[5] = dot4(x_b, t2);    // ps_b
        v[6] = dot4(x_b, w0);    // q0_b
        v[7] = dot4(x_b, w1);    // q1_b

        const float s = oct_reduce(v, lane);

        // Per-lane bias + relu (group g owns slot g)
        float bias;
        if (g & 2)        bias = (g & 1) ? gb1 : gb0;   // slots 2,3,6,7
        else if (g == 0)  bias = fb_a;                  // pd_a
        else if (g == 5)  bias = fb_c;                  // ps_b
        else              bias = fb_b;                  // ps_a (g==1), pd_b (g==4)
        const float w = fmaxf(s + bias, 0.0f);

        // Distribute: lanes<16 get a-row values, lanes>=16 get b-row values
        const float a1 = __shfl_sync(F, w,  4 + hi);    // ws
        const float a2 = __shfl_sync(F, w,  8 + hi);    // v0
        const float a3 = __shfl_sync(F, w, 12 + hi);    // v1
        // Cross: lane0 <- b-row v0/v1 ; lane16 <- a-row v0/v1
        const float b2 = __shfl_sync(F, a2, hi ^ 16);
        const float b3 = __shfl_sync(F, a3, hi ^ 16);

        if (lane == 0) {
            if (p == 0)
                Vnext[warp] = make_float2(a2, a3);       // V[base]
            // row ra: wd_a*V_a + ws_a*V_b
            obuf[warp][2 * p] = make_float2(w * a2 + a1 * b2,
                                            w * a3 + a1 * b3);
        }
        if (lane == 16) {
            if (p > 0) {
                // previous pair's b-row: wd_b*V_b + ws_b*V_a(current pair)
                obuf[warp][2 * p - 1] = make_float2(wdb * v0b + wsb * b2,
                                                    wdb * v1b + wsb * b3);
            }
            wdb = w; wsb = a1; v0b = a2; v1b = a3;
        }

        // Rotate pipeline
        fb_a = fb_c;
        if (p < PAIRS - 1) {
            fb_b = fb_n;
            x_a = x_na; x_b = x_nb;
            t0 = t2; t1 = t_n3; t2 = t_n4;
        }
    }

    // Halo V for the block's last warp
    if (warp == WARPS_PER_BLOCK - 1) {
        int h = base + ROWS_PER_WARP;
        if (h >= N) h -= N;
        const float4 xh = __ldcs(X4 + (size_t)h * 32 + lane);
        float h0 = dot4(xh, xis[lane]);
        float h1 = dot4(xh, xis[32 + lane]);
        float H0, H1;
        quad_reduce(h0, h1, 0.0f, 0.0f, lane, H0, H1);
        if (lane == 0)
            Vnext[WARPS_PER_BLOCK] = make_float2(fmaxf(H0 + gb0, 0.0f),
                                                 fmaxf(H1 + gb1, 0.0f));
    }
    __syncthreads();

    // Emit this warp's final row (pair 7 b-row) from lane 16
    if (lane == 16) {
        const float2 vn = Vnext[warp + 1];
        obuf[warp][ROWS_PER_WARP - 1] = make_float2(wdb * v0b + wsb * vn.x,
                                                    wdb * v1b + wsb * vn.y);
    }
    __syncwarp();

    // Coalesced store: 16 lanes write the warp's 16 float2 results (128B)
    if (lane < ROWS_PER_WARP)
        reinterpret_cast<float2*>(out)[base + lane] = obuf[warp][lane];
}

extern "C" void kernel_launch(void* const* d_in, const int* in_sizes, int n_in,
                              void* d_out, int out_size)
{
    const float* X      = (const float*)d_in[0];
    const float* theta  = (const float*)d_in[1];
    const float* f_bias = (const float*)d_in[2];
    const float* xi     = (const float*)d_in[3];
    const float* g_bias = (const float*)d_in[4];
    float* out = (float*)d_out;

    const int N = in_sizes[2];                   // f_bias has N elements
    const int blocks = N / ROWS_PER_BLOCK;       // 524288 / 128 = 4096

    smf_kernel<<<blocks, WARPS_PER_BLOCK * 32>>>(X, theta, f_bias, xi, g_bias, out, N);
}